// round 9
// baseline (speedup 1.0000x reference)
#include <cuda_runtime.h>
#include <cuda_fp16.h>
#include <cuda_bf16.h>
#include <cstdint>
#include <cstddef>

// ---------------- problem constants ----------------
#define T_TOK 2050
#define TP    2176          // 17*128 padded tokens
#define HDIM  3200          // 25*128
#define IDIM  12800         // 100*128
#define NNT_FC1 100         // IDIM/128  (N tiles)
#define NNT_FC2 25          // HDIM/128
#define NMT   17            // TP/128    (M tiles)
#define PACKY 4             // extra grid rows in fc1 that pack w2

#define BK     64
#define ROWB   80           // 64 data + 16 pad -> conflict-free ldmatrix access
#define TILEB  (128 * ROWB) // 10240
#define STAGEB (2 * TILEB)  // 20480
#define NSTAGE 3
#define SMEM_BYTES (NSTAGE * STAGEB) // 61440

// ---------------- device scratch (allocation-free) ----------------
__device__ __align__(128) int8_t g_w1q[(size_t)IDIM * HDIM];   // [I][H] int8
__device__ __align__(128) int8_t g_w2q[(size_t)HDIM * IDIM];   // [H][I]
__device__ __align__(128) int8_t g_xq [(size_t)TP * HDIM];     // [TP][H]
__device__ __align__(128) int8_t g_actq[(size_t)TP * IDIM];    // [TP][I]
__device__ __align__(128) float  g_gelu[(size_t)TP * IDIM];    // fp32 GELU(fc1)
__device__ float g_amax[TP];

// ---------------- runtime input binding (written by detect_kernel) ----------
// roles: 0 hs, 1 scale_in, 2 w1, 3 w1_scale, 4 b1, 5 w2, 6 w2_scale, 7 b2
__device__ const void* g_ptr[8];
__device__ int g_dt[8];       // dtype: 0=f32, 1=f16, 2=bf16 (roles 1,3,4,6,7)
__device__ int g_outdt;       // output dtype, same coding

struct Ptrs { const void* p[8]; };
struct Szs  { long long s[8]; };

__device__ __forceinline__ float ld_any(const void* p, long long i, int dt) {
    if (dt == 1) return __half2float(((const __half*)p)[i]);
    if (dt == 2) return __bfloat162float(((const __nv_bfloat16*)p)[i]);
    return ((const float*)p)[i];
}

__device__ bool probe_scale(const void* p, int dt, int n) {
    for (int i = 0; i < n; i++) {
        float v = ld_any(p, i, dt);
        if (!(v > 4e-5f && v < 0.03f)) return false;   // also rejects NaN
    }
    return true;
}
__device__ bool probe_bias(const void* p, int dt, int n) {
    int neg = 0, big = 0;
    for (int i = 0; i < n; i++) {
        float v = ld_any(p, i, dt);
        if (!(v == v) || fabsf(v) > 0.5f) return false;
        if (v < 0.0f) neg++;
        if (fabsf(v) > 1e-3f) big++;
    }
    return neg > 0 && big >= n / 4;
}

__global__ void detect_kernel(Ptrs ptrs, Szs sz) {
    if (threadIdx.x != 0 || blockIdx.x != 0) return;
    int hsI = -1, sinI = -1, w[2] = {-1, -1}, p12[2] = {-1, -1}, p3[2] = {-1, -1};
    int nw = 0, n12 = 0, n3 = 0;
    for (int i = 0; i < 8; i++) {
        long long s = sz.s[i];
        if (s == (long long)T_TOK * HDIM) hsI = i;
        else if (s == T_TOK) sinI = i;
        else if (s == (long long)IDIM * HDIM) { if (nw < 2) w[nw] = i; nw++; }
        else if (s == IDIM) { if (n12 < 2) p12[n12] = i; n12++; }
        else if (s == HDIM) { if (n3 < 2) p3[n3] = i; n3++; }
    }
    int role[8], dt[8];
    for (int i = 0; i < 8; i++) { role[i] = i; dt[i] = 0; }
    dt[1] = dt[4] = dt[7] = 1;                       // fallback: dict order, f16
    if (hsI >= 0 && sinI >= 0 && nw == 2 && n12 == 2 && n3 == 2) {
        role[0] = hsI; role[1] = sinI; role[2] = w[0]; role[5] = w[1];
        int prA[2] = { p12[0], p3[0] }, prB[2] = { p12[1], p3[1] };
        int roleS[2] = { 3, 6 }, roleB[2] = { 4, 7 };
        for (int q = 0; q < 2; q++) {
            int a = prA[q], b = prB[q];
            int si = -1, sdt = 0;
            for (int d = 0; d < 3 && si < 0; d++) {          // try f32, f16, bf16
                if      (probe_scale(ptrs.p[a], d, 256)) { si = a; sdt = d; }
                else if (probe_scale(ptrs.p[b], d, 256)) { si = b; sdt = d; }
            }
            if (si < 0) { si = a; sdt = 0; }
            int bi = (si == a) ? b : a;
            int bdt;
            if      (probe_bias(ptrs.p[bi], 1, 256)) bdt = 1;
            else if (probe_bias(ptrs.p[bi], 0, 256)) bdt = 0;
            else if (probe_bias(ptrs.p[bi], 2, 256)) bdt = 2;
            else bdt = 1;
            role[roleS[q]] = si; dt[roleS[q]] = sdt;
            role[roleB[q]] = bi; dt[roleB[q]] = bdt;
        }
        int sdt = 1;
        if      (probe_scale(ptrs.p[sinI], 1, 256)) sdt = 1;
        else if (probe_scale(ptrs.p[sinI], 0, 256)) sdt = 0;
        else if (probe_scale(ptrs.p[sinI], 2, 256)) sdt = 2;
        dt[1] = sdt;
    }
    for (int i = 0; i < 8; i++) { g_ptr[i] = ptrs.p[role[i]]; g_dt[i] = dt[i]; }
    g_outdt = dt[4];
}

// ---------------- PTX helpers ----------------
__device__ __forceinline__ void cp_async16(uint32_t dst, const void* src) {
    asm volatile("cp.async.cg.shared.global [%0], [%1], 16;" :: "r"(dst), "l"(src) : "memory");
}
__device__ __forceinline__ void cp_commit() {
    asm volatile("cp.async.commit_group;" ::: "memory");
}
template <int N>
__device__ __forceinline__ void cp_wait() {
    asm volatile("cp.async.wait_group %0;" :: "n"(N) : "memory");
}
__device__ __forceinline__ uint32_t smem_u32(const void* p) {
    uint32_t a;
    asm("{ .reg .u64 t; cvta.to.shared.u64 t, %1; cvt.u32.u64 %0, t; }" : "=r"(a) : "l"(p));
    return a;
}
__device__ __forceinline__ void ldsm_x4(uint32_t* r, uint32_t addr) {
    asm volatile("ldmatrix.sync.aligned.m8n8.x4.shared.b16 {%0,%1,%2,%3}, [%4];"
                 : "=r"(r[0]), "=r"(r[1]), "=r"(r[2]), "=r"(r[3]) : "r"(addr));
}
__device__ __forceinline__ void mma_s8(int* c, const uint32_t* a, uint32_t b0, uint32_t b1) {
    asm volatile(
        "mma.sync.aligned.m16n8k32.row.col.s32.s8.s8.s32 "
        "{%0,%1,%2,%3}, {%4,%5,%6,%7}, {%8,%9}, {%0,%1,%2,%3};"
        : "+r"(c[0]), "+r"(c[1]), "+r"(c[2]), "+r"(c[3])
        : "r"(a[0]), "r"(a[1]), "r"(a[2]), "r"(a[3]), "r"(b0), "r"(b1));
}
__device__ __forceinline__ float gelu_exact(float x) {
    return 0.5f * x * (1.0f + erff(x * 0.70710678118654752440f));
}

// ---------------- pre-pack: w1 + x int32 -> int8, amax reset (w2 deferred) ----
#define NW_GRP ((size_t)IDIM * HDIM / 4)
#define NX_GRP ((size_t)T_TOK * HDIM / 4)
#define PACK1_TOTAL (NW_GRP + NX_GRP + TP)

__global__ void pack_kernel() {
    size_t i = (size_t)blockIdx.x * blockDim.x + threadIdx.x;
    if (i >= PACK1_TOTAL) return;
    if (i < NW_GRP + NX_GRP) {
        const int* src;
        int8_t* dst;
        size_t g;
        if (i < NW_GRP) { src = (const int*)g_ptr[2]; dst = g_w1q; g = i; }
        else            { src = (const int*)g_ptr[0]; dst = g_xq;  g = i - NW_GRP; }
        int4 v = *reinterpret_cast<const int4*>(src + g * 4);
        uint32_t packed = (v.x & 255) | ((v.y & 255) << 8) | ((v.z & 255) << 16) | ((uint32_t)v.w << 24);
        *reinterpret_cast<uint32_t*>(dst + g * 4) = packed;
    } else {
        g_amax[i - (NW_GRP + NX_GRP)] = 0.0f;
    }
}

// ---------------- int8 tensor-core GEMM, BM=BN=128, BK=64, 256 thr, 3-stage ----
// Warps 4(m) x 2(n), warp tile 32x64 (MF=2, NB=8). 2 CTAs/SM.
// EPI==0: fc1 (A=g_xq, B=g_w1q, K=H) -> fp32 GELU in g_gelu + amax.
//         Grid (100, PACKY+17): y<PACKY blocks pack w2 (overlapped on DRAM pipe).
// EPI==1: fc2 (A=g_actq, B=g_w2q, K=I) -> d_out (dtype per g_outdt). Grid (25, 17).
template <int EPI>
__global__ __launch_bounds__(256, 2) void gemm_kernel(void* out_fc2)
{
    // ---- role-split: w2 packing blocks inside the fc1 launch ----
    if (EPI == 0 && blockIdx.y < PACKY) {
        const int* __restrict__ src = (const int*)g_ptr[5];
        size_t i0 = ((size_t)blockIdx.y * gridDim.x + blockIdx.x) * blockDim.x + threadIdx.x;
        size_t stride = (size_t)PACKY * gridDim.x * blockDim.x;
        for (size_t g = i0; g < NW_GRP; g += stride) {
            int4 v = *reinterpret_cast<const int4*>(src + g * 4);
            uint32_t packed = (v.x & 255) | ((v.y & 255) << 8) |
                              ((v.z & 255) << 16) | ((uint32_t)v.w << 24);
            *reinterpret_cast<uint32_t*>(g_w2q + g * 4) = packed;
        }
        return;
    }

    constexpr int K   = (EPI == 0) ? HDIM : IDIM;
    constexpr int NKI = K / BK;
    const int8_t* __restrict__ A = (EPI == 0) ? g_xq  : g_actq;
    const int8_t* __restrict__ B = (EPI == 0) ? g_w1q : g_w2q;

    const void* wsp  = g_ptr[(EPI == 0) ? 3 : 6]; const int wsdt = g_dt[(EPI == 0) ? 3 : 6];
    const void* bp   = g_ptr[(EPI == 0) ? 4 : 7]; const int bdt  = g_dt[(EPI == 0) ? 4 : 7];
    const void* sinp = g_ptr[1];                  const int sindt = g_dt[1];
    const int outdt = g_outdt;

    extern __shared__ uint8_t smem8[];
    const uint32_t sbase = smem_u32(smem8);

    const int tid  = threadIdx.x;
    const int wid  = tid >> 5, lane = tid & 31;
    const int wm   = wid >> 1, wn = wid & 1;          // 4(m) x 2(n) warps; warp tile 32x64
    const int g    = lane >> 2, tig = lane & 3;
    const int nt   = blockIdx.x;
    const int mt   = (EPI == 0) ? (blockIdx.y - PACKY) : blockIdx.y;

    const size_t arow0 = (size_t)mt * 128;
    const size_t brow0 = (size_t)nt * 128;

    // ldmatrix lane -> (row, 16B column) selector
    const uint32_t rowsel = (uint32_t)(lane & 15) * ROWB + (uint32_t)(lane >> 4) * 16;

    int c[2][8][4];
    #pragma unroll
    for (int mf = 0; mf < 2; mf++)
        #pragma unroll
        for (int nb = 0; nb < 8; nb++)
            #pragma unroll
            for (int j = 0; j < 4; j++) c[mf][nb][j] = 0;

    auto load_stage = [&](int kt, int st) {
        const uint32_t sA = sbase + st * STAGEB;
        const uint32_t sB = sA + TILEB;
        #pragma unroll
        for (int i = 0; i < 2; i++) {
            int id  = tid + i * 256;
            int row = id >> 2, ch = id & 3;
            cp_async16(sA + row * ROWB + ch * 16, A + (arow0 + row) * K + (size_t)kt * BK + ch * 16);
            cp_async16(sB + row * ROWB + ch * 16, B + (brow0 + row) * K + (size_t)kt * BK + ch * 16);
        }
    };

    load_stage(0, 0); cp_commit();
    load_stage(1, 1); cp_commit();

    int st = 0;                       // stage of kt
    for (int kt = 0; kt < NKI; kt++) {
        cp_wait<1>();                 // tile kt resident
        __syncthreads();              // all warps done reading stage (kt+2)%3
        if (kt + 2 < NKI) {
            int st2 = st + 2; if (st2 >= NSTAGE) st2 -= NSTAGE;
            load_stage(kt + 2, st2);
        }
        cp_commit();                  // keep group counting uniform

        const uint32_t sA = sbase + st * STAGEB;
        const uint32_t sB = sA + TILEB;
        #pragma unroll
        for (int ks = 0; ks < 2; ks++) {
            uint32_t a[2][4];
            #pragma unroll
            for (int mf = 0; mf < 2; mf++)
                ldsm_x4(a[mf], sA + (uint32_t)(wm * 32 + mf * 16) * ROWB + ks * 32 + rowsel);
            uint32_t b[4][4];
            #pragma unroll
            for (int p = 0; p < 4; p++)
                ldsm_x4(b[p], sB + (uint32_t)(wn * 64 + p * 16) * ROWB + ks * 32 + rowsel);
            #pragma unroll
            for (int mf = 0; mf < 2; mf++)
                #pragma unroll
                for (int p = 0; p < 4; p++) {
                    mma_s8(c[mf][2 * p],     a[mf], b[p][0], b[p][2]);
                    mma_s8(c[mf][2 * p + 1], a[mf], b[p][1], b[p][3]);
                }
        }
        if (++st == NSTAGE) st = 0;
    }

    // ---------------- epilogue ----------------
    int   rows[4];
    bool  act[4];
    float sx[4], amax_loc[4];
    #pragma unroll
    for (int mf = 0; mf < 2; mf++)
        #pragma unroll
        for (int h = 0; h < 2; h++) {
            int idx = mf * 2 + h;
            int row = mt * 128 + wm * 32 + mf * 16 + g + h * 8;
            rows[idx] = row;
            act[idx]  = (row < T_TOK);
            amax_loc[idx] = 0.0f;
            if (act[idx]) {
                if (EPI == 0) sx[idx] = ld_any(sinp, row, sindt);
                else          sx[idx] = __half2float(__float2half_rn(__fdiv_rn(g_amax[row], 127.0f)));
            } else sx[idx] = 0.0f;
        }

    #pragma unroll
    for (int nb = 0; nb < 8; nb++) {
        int col0 = nt * 128 + wn * 64 + nb * 8 + tig * 2;
        float ws0 = ld_any(wsp, col0, wsdt), ws1 = ld_any(wsp, col0 + 1, wsdt);
        float bb0 = ld_any(bp, col0, bdt),   bb1 = ld_any(bp, col0 + 1, bdt);
        #pragma unroll
        for (int mf = 0; mf < 2; mf++)
            #pragma unroll
            for (int h = 0; h < 2; h++) {
                int idx = mf * 2 + h;
                if (!act[idx]) continue;
                float v0 = (float)c[mf][nb][h * 2 + 0] * sx[idx] * ws0 + bb0;
                float v1 = (float)c[mf][nb][h * 2 + 1] * sx[idx] * ws1 + bb1;
                __half h0 = __float2half_rn(v0), h1 = __float2half_rn(v1);
                if (EPI == 0) {
                    // exact reference dataflow: g = gelu_fp32(fp16(fc1)), stored fp32
                    float g0 = gelu_exact(__half2float(h0));
                    float g1 = gelu_exact(__half2float(h1));
                    *reinterpret_cast<float2*>(&g_gelu[(size_t)rows[idx] * IDIM + col0]) =
                        make_float2(g0, g1);
                    amax_loc[idx] = fmaxf(amax_loc[idx], fmaxf(fabsf(g0), fabsf(g1)));
                } else {
                    size_t o = (size_t)rows[idx] * HDIM + col0;
                    if (outdt == 1) {
                        *reinterpret_cast<__half2*>((__half*)out_fc2 + o) = __halves2half2(h0, h1);
                    } else if (outdt == 0) {
                        ((float*)out_fc2)[o]     = __half2float(h0);
                        ((float*)out_fc2)[o + 1] = __half2float(h1);
                    } else {
                        ((__nv_bfloat16*)out_fc2)[o]     = __float2bfloat16(__half2float(h0));
                        ((__nv_bfloat16*)out_fc2)[o + 1] = __float2bfloat16(__half2float(h1));
                    }
                }
            }
    }
    if (EPI == 0) {
        #pragma unroll
        for (int idx = 0; idx < 4; idx++)
            if (act[idx])
                atomicMax(reinterpret_cast<int*>(&g_amax[rows[idx]]), __float_as_int(amax_loc[idx]));
    }
}

// ---------------- quant: fp32 GELU values -> int8 (memory-bound) ----------------
__global__ void quant_kernel() {
    size_t i = (size_t)blockIdx.x * blockDim.x + threadIdx.x;   // group of 4 elems
    if (i >= (size_t)TP * IDIM / 4) return;
    size_t e = i * 4;
    int row = (int)(e / IDIM);
    uint32_t packed = 0;
    if (row < T_TOK) {
        float am = g_amax[row];
        float s  = fmaxf(__half2float(__float2half_rn(__fdiv_rn(am, 127.0f))), 1e-8f);
        float rs = __fdiv_rn(1.0f, s);
        float4 gv = *reinterpret_cast<const float4*>(&g_gelu[e]);
        int q0 = (int)fminf(fmaxf(rintf(gv.x * rs), -128.0f), 127.0f);
        int q1 = (int)fminf(fmaxf(rintf(gv.y * rs), -128.0f), 127.0f);
        int q2 = (int)fminf(fmaxf(rintf(gv.z * rs), -128.0f), 127.0f);
        int q3 = (int)fminf(fmaxf(rintf(gv.w * rs), -128.0f), 127.0f);
        packed = (uint32_t)(q0 & 255) | ((uint32_t)(q1 & 255) << 8) |
                 ((uint32_t)(q2 & 255) << 16) | ((uint32_t)(q3 & 255) << 24);
    }
    *reinterpret_cast<uint32_t*>(g_actq + e) = packed;
}

// ---------------- host launcher ----------------
extern "C" void kernel_launch(void* const* d_in, const int* in_sizes, int n_in,
                              void* d_out, int out_size) {
    Ptrs ptrs; Szs szs;
    for (int i = 0; i < 8; i++) {
        ptrs.p[i] = (i < n_in) ? d_in[i] : nullptr;
        szs.s[i]  = (i < n_in) ? (long long)in_sizes[i] : 0;
    }

    cudaFuncSetAttribute(gemm_kernel<0>, cudaFuncAttributeMaxDynamicSharedMemorySize, SMEM_BYTES);
    cudaFuncSetAttribute(gemm_kernel<1>, cudaFuncAttributeMaxDynamicSharedMemorySize, SMEM_BYTES);

    detect_kernel<<<1, 32>>>(ptrs, szs);
    {
        size_t total = PACK1_TOTAL;
        int blocks = (int)((total + 255) / 256);
        pack_kernel<<<blocks, 256>>>();
    }
    // fc1: y rows [0,PACKY) pack w2 (overlapped), y rows [PACKY, PACKY+17) do GEMM
    gemm_kernel<0><<<dim3(NNT_FC1, PACKY + NMT), 256, SMEM_BYTES>>>(nullptr);
    {
        size_t total = (size_t)TP * IDIM / 4;
        int blocks = (int)((total + 255) / 256);
        quant_kernel<<<blocks, 256>>>();
    }
    gemm_kernel<1><<<dim3(NNT_FC2, NMT), 256, SMEM_BYTES>>>(d_out);
}

// round 10
// speedup vs baseline: 1.0983x; 1.0983x over previous
#include <cuda_runtime.h>
#include <cuda_fp16.h>
#include <cuda_bf16.h>
#include <cstdint>
#include <cstddef>

// ---------------- problem constants ----------------
#define T_TOK 2050
#define TP    2176          // 17*128 padded tokens
#define HDIM  3200          // 25*128
#define IDIM  12800         // 100*128
#define NMT   17            // TP/128
#define NNT_FC1 100         // IDIM/128
#define NNT_FC2 25          // HDIM/128

#define BK     128
#define ROWB   144          // 128 data + 16 pad -> conflict-free ldmatrix (16*i mod 128 distinct)
#define TILEB  (128 * ROWB) // 18432
#define STAGEB (2 * TILEB)  // 36864 (A tile + B tile)
#define NSTAGE 2
#define SMEM_BYTES (NSTAGE * STAGEB) // 73728 (needs opt-in attribute; 2 CTAs/SM = 147KB)

// ---------------- device scratch (allocation-free) ----------------
__device__ __align__(128) int8_t g_w1q[(size_t)IDIM * HDIM];   // [I][H] int8
__device__ __align__(128) int8_t g_w2q[(size_t)HDIM * IDIM];   // [H][I]
__device__ __align__(128) int8_t g_xq [(size_t)TP * HDIM];     // [TP][H]
__device__ __align__(128) int8_t g_actq[(size_t)TP * IDIM];    // [TP][I]
__device__ __align__(128) __half g_fc1 [(size_t)TP * IDIM];    // fp16 PRE-GELU fc1 [TP][I]
__device__ float g_amax[TP];

// ---------------- runtime input binding (written by detect_kernel) ----------
// roles: 0 hs, 1 scale_in, 2 w1, 3 w1_scale, 4 b1, 5 w2, 6 w2_scale, 7 b2
__device__ const void* g_ptr[8];
__device__ int g_dt[8];       // dtype: 0=f32, 1=f16, 2=bf16 (roles 1,3,4,6,7)
__device__ int g_outdt;       // output dtype, same coding

struct Ptrs { const void* p[8]; };
struct Szs  { long long s[8]; };

__device__ __forceinline__ float ld_any(const void* p, long long i, int dt) {
    if (dt == 1) return __half2float(((const __half*)p)[i]);
    if (dt == 2) return __bfloat162float(((const __nv_bfloat16*)p)[i]);
    return ((const float*)p)[i];
}

__device__ bool probe_scale(const void* p, int dt, int n) {
    for (int i = 0; i < n; i++) {
        float v = ld_any(p, i, dt);
        if (!(v > 4e-5f && v < 0.03f)) return false;   // also rejects NaN
    }
    return true;
}
__device__ bool probe_bias(const void* p, int dt, int n) {
    int neg = 0, big = 0;
    for (int i = 0; i < n; i++) {
        float v = ld_any(p, i, dt);
        if (!(v == v) || fabsf(v) > 0.5f) return false;
        if (v < 0.0f) neg++;
        if (fabsf(v) > 1e-3f) big++;
    }
    return neg > 0 && big >= n / 4;
}

__global__ void detect_kernel(Ptrs ptrs, Szs sz) {
    if (threadIdx.x != 0 || blockIdx.x != 0) return;
    int hsI = -1, sinI = -1, w[2] = {-1, -1}, p12[2] = {-1, -1}, p3[2] = {-1, -1};
    int nw = 0, n12 = 0, n3 = 0;
    for (int i = 0; i < 8; i++) {
        long long s = sz.s[i];
        if (s == (long long)T_TOK * HDIM) hsI = i;
        else if (s == T_TOK) sinI = i;
        else if (s == (long long)IDIM * HDIM) { if (nw < 2) w[nw] = i; nw++; }
        else if (s == IDIM) { if (n12 < 2) p12[n12] = i; n12++; }
        else if (s == HDIM) { if (n3 < 2) p3[n3] = i; n3++; }
    }
    int role[8], dt[8];
    for (int i = 0; i < 8; i++) { role[i] = i; dt[i] = 0; }
    dt[1] = dt[4] = dt[7] = 1;                       // fallback: dict order, f16
    if (hsI >= 0 && sinI >= 0 && nw == 2 && n12 == 2 && n3 == 2) {
        role[0] = hsI; role[1] = sinI; role[2] = w[0]; role[5] = w[1];
        int prA[2] = { p12[0], p3[0] }, prB[2] = { p12[1], p3[1] };
        int roleS[2] = { 3, 6 }, roleB[2] = { 4, 7 };
        for (int q = 0; q < 2; q++) {
            int a = prA[q], b = prB[q];
            int si = -1, sdt = 0;
            for (int d = 0; d < 3 && si < 0; d++) {          // try f32, f16, bf16
                if      (probe_scale(ptrs.p[a], d, 256)) { si = a; sdt = d; }
                else if (probe_scale(ptrs.p[b], d, 256)) { si = b; sdt = d; }
            }
            if (si < 0) { si = a; sdt = 0; }
            int bi = (si == a) ? b : a;
            int bdt;
            if      (probe_bias(ptrs.p[bi], 1, 256)) bdt = 1;
            else if (probe_bias(ptrs.p[bi], 0, 256)) bdt = 0;
            else if (probe_bias(ptrs.p[bi], 2, 256)) bdt = 2;
            else bdt = 1;
            role[roleS[q]] = si; dt[roleS[q]] = sdt;
            role[roleB[q]] = bi; dt[roleB[q]] = bdt;
        }
        int sdt = 1;
        if      (probe_scale(ptrs.p[sinI], 1, 256)) sdt = 1;
        else if (probe_scale(ptrs.p[sinI], 0, 256)) sdt = 0;
        else if (probe_scale(ptrs.p[sinI], 2, 256)) sdt = 2;
        dt[1] = sdt;
    }
    for (int i = 0; i < 8; i++) { g_ptr[i] = ptrs.p[role[i]]; g_dt[i] = dt[i]; }
    g_outdt = dt[4];
}

// ---------------- PTX helpers ----------------
__device__ __forceinline__ void cp_async16(uint32_t dst, const void* src) {
    asm volatile("cp.async.cg.shared.global [%0], [%1], 16;" :: "r"(dst), "l"(src) : "memory");
}
__device__ __forceinline__ void cp_commit() {
    asm volatile("cp.async.commit_group;" ::: "memory");
}
template <int N>
__device__ __forceinline__ void cp_wait() {
    asm volatile("cp.async.wait_group %0;" :: "n"(N) : "memory");
}
__device__ __forceinline__ uint32_t smem_u32(const void* p) {
    uint32_t a;
    asm("{ .reg .u64 t; cvta.to.shared.u64 t, %1; cvt.u32.u64 %0, t; }" : "=r"(a) : "l"(p));
    return a;
}
__device__ __forceinline__ void ldsm_x4(uint32_t* r, uint32_t addr) {
    asm volatile("ldmatrix.sync.aligned.m8n8.x4.shared.b16 {%0,%1,%2,%3}, [%4];"
                 : "=r"(r[0]), "=r"(r[1]), "=r"(r[2]), "=r"(r[3]) : "r"(addr));
}
__device__ __forceinline__ void mma_s8(int* c, const uint32_t* a, uint32_t b0, uint32_t b1) {
    asm volatile(
        "mma.sync.aligned.m16n8k32.row.col.s32.s8.s8.s32 "
        "{%0,%1,%2,%3}, {%4,%5,%6,%7}, {%8,%9}, {%0,%1,%2,%3};"
        : "+r"(c[0]), "+r"(c[1]), "+r"(c[2]), "+r"(c[3])
        : "r"(a[0]), "r"(a[1]), "r"(a[2]), "r"(a[3]), "r"(b0), "r"(b1));
}
__device__ __forceinline__ float gelu_exact(float x) {
    return 0.5f * x * (1.0f + erff(x * 0.70710678118654752440f));
}

// ---------------- pack: int32 -> int8 linear (w1, w2, x), amax reset ----------
#define NW_GRP ((size_t)IDIM * HDIM / 4)
#define NX_GRP ((size_t)T_TOK * HDIM / 4)
#define PACK_TOTAL (2 * NW_GRP + NX_GRP + TP)

__global__ void pack_kernel() {
    size_t i = (size_t)blockIdx.x * blockDim.x + threadIdx.x;
    if (i >= PACK_TOTAL) return;
    if (i < 2 * NW_GRP + NX_GRP) {
        const int* src;
        int8_t* dst;
        size_t g;
        if (i < NW_GRP)          { src = (const int*)g_ptr[2]; dst = g_w1q; g = i; }
        else if (i < 2 * NW_GRP) { src = (const int*)g_ptr[5]; dst = g_w2q; g = i - NW_GRP; }
        else                     { src = (const int*)g_ptr[0]; dst = g_xq;  g = i - 2 * NW_GRP; }
        int4 v = *reinterpret_cast<const int4*>(src + g * 4);
        uint32_t packed = (v.x & 255) | ((v.y & 255) << 8) | ((v.z & 255) << 16) | ((uint32_t)v.w << 24);
        *reinterpret_cast<uint32_t*>(dst + g * 4) = packed;
    } else {
        g_amax[i - (2 * NW_GRP + NX_GRP)] = 0.0f;
    }
}

// ---------------- int8 tensor-core GEMM, BM=BN=128, BK=128, 256 thr, 2-stage ----
// Warps 4(m) x 2(n), warp tile 32x64 (MF=2, NB=8). 2 CTAs/SM.
// One __syncthreads per 128-deep K chunk (halved barrier count vs BK=64).
// EPI==0: fc1 (A=g_xq, B=g_w1q, K=H)  -> fp16 PRE-GELU fc1 in g_fc1 + GELU amax
// EPI==1: fc2 (A=g_actq, B=g_w2q, K=I) -> d_out (dtype per g_outdt)
template <int EPI>
__global__ __launch_bounds__(256, 2) void gemm_kernel(void* out_fc2)
{
    constexpr int K   = (EPI == 0) ? HDIM : IDIM;
    constexpr int NKI = K / BK;                       // fc1: 25, fc2: 100
    const int8_t* __restrict__ A = (EPI == 0) ? g_xq  : g_actq;
    const int8_t* __restrict__ B = (EPI == 0) ? g_w1q : g_w2q;

    const void* wsp  = g_ptr[(EPI == 0) ? 3 : 6]; const int wsdt = g_dt[(EPI == 0) ? 3 : 6];
    const void* bp   = g_ptr[(EPI == 0) ? 4 : 7]; const int bdt  = g_dt[(EPI == 0) ? 4 : 7];
    const void* sinp = g_ptr[1];                  const int sindt = g_dt[1];
    const int outdt = g_outdt;

    extern __shared__ uint8_t smem8[];
    const uint32_t sbase = smem_u32(smem8);

    const int tid  = threadIdx.x;
    const int wid  = tid >> 5, lane = tid & 31;
    const int wm   = wid >> 1, wn = wid & 1;          // 4(m) x 2(n) warps; warp tile 32x64
    const int g    = lane >> 2, tig = lane & 3;
    const int nt   = blockIdx.x, mt = blockIdx.y;

    const size_t arow0 = (size_t)mt * 128;
    const size_t brow0 = (size_t)nt * 128;

    // ldmatrix lane -> (row, 16B column) selector
    const uint32_t rowsel = (uint32_t)(lane & 15) * ROWB + (uint32_t)(lane >> 4) * 16;

    int c[2][8][4];
    #pragma unroll
    for (int mf = 0; mf < 2; mf++)
        #pragma unroll
        for (int nb = 0; nb < 8; nb++)
            #pragma unroll
            for (int j = 0; j < 4; j++) c[mf][nb][j] = 0;

    // per stage: A 128 rows x 128B + B 128 rows x 128B = 2048 x 16B; 8 per thread
    auto load_stage = [&](int kt, int st) {
        const uint32_t sA = sbase + st * STAGEB;
        const uint32_t sB = sA + TILEB;
        #pragma unroll
        for (int i = 0; i < 4; i++) {
            int id  = tid + i * 256;
            int row = id >> 3, ch = id & 7;
            cp_async16(sA + row * ROWB + ch * 16,
                       A + (arow0 + row) * K + (size_t)kt * BK + ch * 16);
        }
        #pragma unroll
        for (int i = 0; i < 4; i++) {
            int id  = tid + i * 256;
            int row = id >> 3, ch = id & 7;
            cp_async16(sB + row * ROWB + ch * 16,
                       B + (brow0 + row) * K + (size_t)kt * BK + ch * 16);
        }
    };

    load_stage(0, 0);
    cp_commit();

    for (int kt = 0; kt < NKI; kt++) {
        cp_wait<0>();                 // stage kt resident
        __syncthreads();              // all warps finished reading stage (kt+1)&1 (iter kt-1)
        if (kt + 1 < NKI) {
            load_stage(kt + 1, (kt + 1) & 1);   // overlaps with compute below
            cp_commit();
        }

        const uint32_t sA = sbase + (kt & 1) * STAGEB;
        const uint32_t sB = sA + TILEB;
        #pragma unroll
        for (int ks = 0; ks < 4; ks++) {
            uint32_t a[2][4];
            #pragma unroll
            for (int mf = 0; mf < 2; mf++)
                ldsm_x4(a[mf], sA + (uint32_t)(wm * 32 + mf * 16) * ROWB + ks * 32 + rowsel);
            uint32_t b[4][4];
            #pragma unroll
            for (int p = 0; p < 4; p++)
                ldsm_x4(b[p], sB + (uint32_t)(wn * 64 + p * 16) * ROWB + ks * 32 + rowsel);
            #pragma unroll
            for (int mf = 0; mf < 2; mf++)
                #pragma unroll
                for (int p = 0; p < 4; p++) {
                    mma_s8(c[mf][2 * p],     a[mf], b[p][0], b[p][2]);
                    mma_s8(c[mf][2 * p + 1], a[mf], b[p][1], b[p][3]);
                }
        }
    }

    // ---------------- epilogue ----------------
    int   rows[4];
    bool  act[4];
    float sx[4], amax_loc[4];
    #pragma unroll
    for (int mf = 0; mf < 2; mf++)
        #pragma unroll
        for (int h = 0; h < 2; h++) {
            int idx = mf * 2 + h;
            int row = mt * 128 + wm * 32 + mf * 16 + g + h * 8;
            rows[idx] = row;
            act[idx]  = (row < T_TOK);
            amax_loc[idx] = 0.0f;
            if (act[idx]) {
                if (EPI == 0) sx[idx] = ld_any(sinp, row, sindt);
                else          sx[idx] = __half2float(__float2half_rn(__fdiv_rn(g_amax[row], 127.0f)));
            } else sx[idx] = 0.0f;
        }

    #pragma unroll
    for (int nb = 0; nb < 8; nb++) {
        int col0 = nt * 128 + wn * 64 + nb * 8 + tig * 2;
        float ws0 = ld_any(wsp, col0, wsdt), ws1 = ld_any(wsp, col0 + 1, wsdt);
        float bb0 = ld_any(bp, col0, bdt),   bb1 = ld_any(bp, col0 + 1, bdt);
        #pragma unroll
        for (int mf = 0; mf < 2; mf++)
            #pragma unroll
            for (int h = 0; h < 2; h++) {
                int idx = mf * 2 + h;
                if (!act[idx]) continue;
                float v0 = (float)c[mf][nb][h * 2 + 0] * sx[idx] * ws0 + bb0;
                float v1 = (float)c[mf][nb][h * 2 + 1] * sx[idx] * ws1 + bb1;
                __half h0 = __float2half_rn(v0), h1 = __float2half_rn(v1);
                if (EPI == 0) {
                    // store PRE-GELU fp16 fc1 (exact reference intermediate);
                    // gelu here only feeds the amax reduction
                    *reinterpret_cast<__half2*>(&g_fc1[(size_t)rows[idx] * IDIM + col0]) =
                        __halves2half2(h0, h1);
                    float g0 = gelu_exact(__half2float(h0));
                    float g1 = gelu_exact(__half2float(h1));
                    amax_loc[idx] = fmaxf(amax_loc[idx], fmaxf(fabsf(g0), fabsf(g1)));
                } else {
                    size_t o = (size_t)rows[idx] * HDIM + col0;
                    if (outdt == 1) {
                        *reinterpret_cast<__half2*>((__half*)out_fc2 + o) = __halves2half2(h0, h1);
                    } else if (outdt == 0) {
                        ((float*)out_fc2)[o]     = __half2float(h0);
                        ((float*)out_fc2)[o + 1] = __half2float(h1);
                    } else {
                        ((__nv_bfloat16*)out_fc2)[o]     = __float2bfloat16(__half2float(h0));
                        ((__nv_bfloat16*)out_fc2)[o + 1] = __float2bfloat16(__half2float(h1));
                    }
                }
            }
    }
    if (EPI == 0) {
        #pragma unroll
        for (int idx = 0; idx < 4; idx++)
            if (act[idx])
                atomicMax(reinterpret_cast<int*>(&g_amax[rows[idx]]), __float_as_int(amax_loc[idx]));
    }
}

// ---------------- quant: fp16 fc1 -> GELU(fp32) -> int8 ----------------
__global__ void quant_kernel() {
    size_t i = (size_t)blockIdx.x * blockDim.x + threadIdx.x;   // group of 8 elems
    if (i >= (size_t)TP * IDIM / 8) return;
    size_t e = i * 8;
    int row = (int)(e / IDIM);
    uint2 outv = make_uint2(0u, 0u);
    if (row < T_TOK) {
        float am = g_amax[row];
        float s  = fmaxf(__half2float(__float2half_rn(__fdiv_rn(am, 127.0f))), 1e-8f);
        float rs = __fdiv_rn(1.0f, s);
        uint4 raw = *reinterpret_cast<const uint4*>(&g_fc1[e]);
        const __half2* hp = reinterpret_cast<const __half2*>(&raw);
        uint32_t word[2] = {0u, 0u};
        #pragma unroll
        for (int w = 0; w < 2; w++) {
            #pragma unroll
            for (int j = 0; j < 2; j++) {
                __half2 h = hp[w * 2 + j];
                float g0 = gelu_exact(__half2float(__low2half(h)));
                float g1 = gelu_exact(__half2float(__high2half(h)));
                int q0 = (int)fminf(fmaxf(rintf(g0 * rs), -128.0f), 127.0f);
                int q1 = (int)fminf(fmaxf(rintf(g1 * rs), -128.0f), 127.0f);
                word[w] |= ((uint32_t)(q0 & 255)) << (16 * j);
                word[w] |= ((uint32_t)(q1 & 255)) << (16 * j + 8);
            }
        }
        outv = make_uint2(word[0], word[1]);
    }
    *reinterpret_cast<uint2*>(g_actq + e) = outv;
}

// ---------------- host launcher ----------------
extern "C" void kernel_launch(void* const* d_in, const int* in_sizes, int n_in,
                              void* d_out, int out_size) {
    Ptrs ptrs; Szs szs;
    for (int i = 0; i < 8; i++) {
        ptrs.p[i] = (i < n_in) ? d_in[i] : nullptr;
        szs.s[i]  = (i < n_in) ? (long long)in_sizes[i] : 0;
    }

    cudaFuncSetAttribute(gemm_kernel<0>, cudaFuncAttributeMaxDynamicSharedMemorySize, SMEM_BYTES);
    cudaFuncSetAttribute(gemm_kernel<1>, cudaFuncAttributeMaxDynamicSharedMemorySize, SMEM_BYTES);

    detect_kernel<<<1, 32>>>(ptrs, szs);
    {
        size_t total = PACK_TOTAL;
        int blocks = (int)((total + 255) / 256);
        pack_kernel<<<blocks, 256>>>();
    }
    gemm_kernel<0><<<dim3(NNT_FC1, NMT), 256, SMEM_BYTES>>>(nullptr);
    {
        size_t total = (size_t)TP * IDIM / 8;
        int blocks = (int)((total + 255) / 256);
        quant_kernel<<<blocks, 256>>>();
    }
    gemm_kernel<1><<<dim3(NNT_FC2, NMT), 256, SMEM_BYTES>>>(d_out);
}

// round 13
// speedup vs baseline: 1.1206x; 1.0203x over previous
#include <cuda_runtime.h>
#include <cuda_fp16.h>
#include <cuda_bf16.h>
#include <cstdint>
#include <cstddef>

// ---------------- problem constants ----------------
#define T_TOK 2050
#define TP    2176          // 17*128 padded tokens
#define HDIM  3200          // 25*128
#define IDIM  12800         // 100*128
#define NMT   17            // TP/128
#define NNT_FC1 100         // IDIM/128
#define NNT_FC2 25          // HDIM/128

#define BK     128
#define ROWB   144          // 128 data + 16 pad -> conflict-free ldmatrix (16*i mod 128 distinct)
#define TILEB  (128 * ROWB) // 18432
#define STAGEB (2 * TILEB)  // 36864 (A tile + B tile)
#define NSTAGE 2
#define SMEM_BYTES (NSTAGE * STAGEB) // 73728 (opt-in; 2 CTAs/SM = 147KB) — round-10 proven config

// GELU stationary point x* = -0.7517916...; T1 < x* < T2, no fp16 value in (T1,T2)
#define GELU_T1 (-0.751800f)
#define GELU_T2 (-0.751785f)

// ---------------- device scratch (allocation-free) ----------------
__device__ __align__(128) int8_t g_w1q[(size_t)IDIM * HDIM];   // [I][H] int8
__device__ __align__(128) int8_t g_w2q[(size_t)HDIM * IDIM];   // [H][I]
__device__ __align__(128) int8_t g_xq [(size_t)TP * HDIM];     // [TP][H]
__device__ __align__(128) int8_t g_actq[(size_t)TP * IDIM];    // [TP][I]
__device__ __align__(128) __half g_fc1 [(size_t)TP * IDIM];    // fp16 PRE-GELU fc1 [TP][I]
__device__ float g_amax[TP];

// ---------------- runtime input binding (written by detect_kernel) ----------
// roles: 0 hs, 1 scale_in, 2 w1, 3 w1_scale, 4 b1, 5 w2, 6 w2_scale, 7 b2
__device__ const void* g_ptr[8];
__device__ int g_dt[8];       // dtype: 0=f32, 1=f16, 2=bf16 (roles 1,3,4,6,7)
__device__ int g_outdt;       // output dtype, same coding

struct Ptrs { const void* p[8]; };
struct Szs  { long long s[8]; };

__device__ __forceinline__ float ld_any(const void* p, long long i, int dt) {
    if (dt == 1) return __half2float(((const __half*)p)[i]);
    if (dt == 2) return __bfloat162float(((const __nv_bfloat16*)p)[i]);
    return ((const float*)p)[i];
}

__device__ bool probe_scale(const void* p, int dt, int n) {
    for (int i = 0; i < n; i++) {
        float v = ld_any(p, i, dt);
        if (!(v > 4e-5f && v < 0.03f)) return false;   // also rejects NaN
    }
    return true;
}
__device__ bool probe_bias(const void* p, int dt, int n) {
    int neg = 0, big = 0;
    for (int i = 0; i < n; i++) {
        float v = ld_any(p, i, dt);
        if (!(v == v) || fabsf(v) > 0.5f) return false;
        if (v < 0.0f) neg++;
        if (fabsf(v) > 1e-3f) big++;
    }
    return neg > 0 && big >= n / 4;
}

__global__ void detect_kernel(Ptrs ptrs, Szs sz) {
    if (threadIdx.x != 0 || blockIdx.x != 0) return;
    int hsI = -1, sinI = -1, w[2] = {-1, -1}, p12[2] = {-1, -1}, p3[2] = {-1, -1};
    int nw = 0, n12 = 0, n3 = 0;
    for (int i = 0; i < 8; i++) {
        long long s = sz.s[i];
        if (s == (long long)T_TOK * HDIM) hsI = i;
        else if (s == T_TOK) sinI = i;
        else if (s == (long long)IDIM * HDIM) { if (nw < 2) w[nw] = i; nw++; }
        else if (s == IDIM) { if (n12 < 2) p12[n12] = i; n12++; }
        else if (s == HDIM) { if (n3 < 2) p3[n3] = i; n3++; }
    }
    int role[8], dt[8];
    for (int i = 0; i < 8; i++) { role[i] = i; dt[i] = 0; }
    dt[1] = dt[4] = dt[7] = 1;                       // fallback: dict order, f16
    if (hsI >= 0 && sinI >= 0 && nw == 2 && n12 == 2 && n3 == 2) {
        role[0] = hsI; role[1] = sinI; role[2] = w[0]; role[5] = w[1];
        int prA[2] = { p12[0], p3[0] }, prB[2] = { p12[1], p3[1] };
        int roleS[2] = { 3, 6 }, roleB[2] = { 4, 7 };
        for (int q = 0; q < 2; q++) {
            int a = prA[q], b = prB[q];
            int si = -1, sdt = 0;
            for (int d = 0; d < 3 && si < 0; d++) {          // try f32, f16, bf16
                if      (probe_scale(ptrs.p[a], d, 256)) { si = a; sdt = d; }
                else if (probe_scale(ptrs.p[b], d, 256)) { si = b; sdt = d; }
            }
            if (si < 0) { si = a; sdt = 0; }
            int bi = (si == a) ? b : a;
            int bdt;
            if      (probe_bias(ptrs.p[bi], 1, 256)) bdt = 1;
            else if (probe_bias(ptrs.p[bi], 0, 256)) bdt = 0;
            else if (probe_bias(ptrs.p[bi], 2, 256)) bdt = 2;
            else bdt = 1;
            role[roleS[q]] = si; dt[roleS[q]] = sdt;
            role[roleB[q]] = bi; dt[roleB[q]] = bdt;
        }
        int sdt = 1;
        if      (probe_scale(ptrs.p[sinI], 1, 256)) sdt = 1;
        else if (probe_scale(ptrs.p[sinI], 0, 256)) sdt = 0;
        else if (probe_scale(ptrs.p[sinI], 2, 256)) sdt = 2;
        dt[1] = sdt;
    }
    for (int i = 0; i < 8; i++) { g_ptr[i] = ptrs.p[role[i]]; g_dt[i] = dt[i]; }
    g_outdt = dt[4];
}

// ---------------- PTX helpers ----------------
__device__ __forceinline__ void cp_async16(uint32_t dst, const void* src) {
    asm volatile("cp.async.cg.shared.global [%0], [%1], 16;" :: "r"(dst), "l"(src) : "memory");
}
__device__ __forceinline__ void cp_commit() {
    asm volatile("cp.async.commit_group;" ::: "memory");
}
template <int N>
__device__ __forceinline__ void cp_wait() {
    asm volatile("cp.async.wait_group %0;" :: "n"(N) : "memory");
}
__device__ __forceinline__ uint32_t smem_u32(const void* p) {
    uint32_t a;
    asm("{ .reg .u64 t; cvta.to.shared.u64 t, %1; cvt.u32.u64 %0, t; }" : "=r"(a) : "l"(p));
    return a;
}
__device__ __forceinline__ void ldsm_x4(uint32_t* r, uint32_t addr) {
    asm volatile("ldmatrix.sync.aligned.m8n8.x4.shared.b16 {%0,%1,%2,%3}, [%4];"
                 : "=r"(r[0]), "=r"(r[1]), "=r"(r[2]), "=r"(r[3]) : "r"(addr));
}
__device__ __forceinline__ void mma_s8(int* c, const uint32_t* a, uint32_t b0, uint32_t b1) {
    asm volatile(
        "mma.sync.aligned.m16n8k32.row.col.s32.s8.s8.s32 "
        "{%0,%1,%2,%3}, {%4,%5,%6,%7}, {%8,%9}, {%0,%1,%2,%3};"
        : "+r"(c[0]), "+r"(c[1]), "+r"(c[2]), "+r"(c[3])
        : "r"(a[0]), "r"(a[1]), "r"(a[2]), "r"(a[3]), "r"(b0), "r"(b1));
}
__device__ __forceinline__ float gelu_exact(float x) {
    return 0.5f * x * (1.0f + erff(x * 0.70710678118654752440f));
}

// ---------------- pack: int32 -> int8 linear (w1, w2, x), amax reset ----------
#define NW_GRP ((size_t)IDIM * HDIM / 4)
#define NX_GRP ((size_t)T_TOK * HDIM / 4)
#define PACK_TOTAL (2 * NW_GRP + NX_GRP + TP)

__global__ void pack_kernel() {
    size_t i = (size_t)blockIdx.x * blockDim.x + threadIdx.x;
    if (i >= PACK_TOTAL) return;
    if (i < 2 * NW_GRP + NX_GRP) {
        const int* src;
        int8_t* dst;
        size_t g;
        if (i < NW_GRP)          { src = (const int*)g_ptr[2]; dst = g_w1q; g = i; }
        else if (i < 2 * NW_GRP) { src = (const int*)g_ptr[5]; dst = g_w2q; g = i - NW_GRP; }
        else                     { src = (const int*)g_ptr[0]; dst = g_xq;  g = i - 2 * NW_GRP; }
        // evict-first streaming read: keep L2 free for packed weights
        int4 v = __ldcs(reinterpret_cast<const int4*>(src + g * 4));
        uint32_t packed = (v.x & 255) | ((v.y & 255) << 8) | ((v.z & 255) << 16) | ((uint32_t)v.w << 24);
        *reinterpret_cast<uint32_t*>(dst + g * 4) = packed;
    } else {
        g_amax[i - (2 * NW_GRP + NX_GRP)] = 0.0f;
    }
}

// ---------------- int8 tensor-core GEMM, BM=BN=128, BK=128, 256 thr, 2-stage ----
// Warps 4(m) x 2(n), warp tile 32x64 (MF=2, NB=8). 2 CTAs/SM. (round-10 proven skeleton)
// EPI==0: fc1 (A=g_xq, B=g_w1q, K=H)  -> fp16 PRE-GELU fc1 in g_fc1 + amax (erf-free tracking)
// EPI==1: fc2 (A=g_actq, B=g_w2q, K=I) -> d_out (dtype per g_outdt)
template <int EPI>
__global__ __launch_bounds__(256, 2) void gemm_kernel(void* out_fc2)
{
    constexpr int K   = (EPI == 0) ? HDIM : IDIM;
    constexpr int NKI = K / BK;                       // fc1: 25, fc2: 100
    const int8_t* __restrict__ A = (EPI == 0) ? g_xq  : g_actq;
    const int8_t* __restrict__ B = (EPI == 0) ? g_w1q : g_w2q;

    const void* wsp  = g_ptr[(EPI == 0) ? 3 : 6]; const int wsdt = g_dt[(EPI == 0) ? 3 : 6];
    const void* bp   = g_ptr[(EPI == 0) ? 4 : 7]; const int bdt  = g_dt[(EPI == 0) ? 4 : 7];
    const void* sinp = g_ptr[1];                  const int sindt = g_dt[1];
    const int outdt = g_outdt;

    extern __shared__ uint8_t smem8[];
    const uint32_t sbase = smem_u32(smem8);

    const int tid  = threadIdx.x;
    const int wid  = tid >> 5, lane = tid & 31;
    const int wm   = wid >> 1, wn = wid & 1;          // 4(m) x 2(n) warps; warp tile 32x64
    const int g    = lane >> 2, tig = lane & 3;
    const int nt   = blockIdx.x, mt = blockIdx.y;

    const size_t arow0 = (size_t)mt * 128;
    const size_t brow0 = (size_t)nt * 128;

    // ldmatrix lane -> (row, 16B column) selector
    const uint32_t rowsel = (uint32_t)(lane & 15) * ROWB + (uint32_t)(lane >> 4) * 16;

    int c[2][8][4];
    #pragma unroll
    for (int mf = 0; mf < 2; mf++)
        #pragma unroll
        for (int nb = 0; nb < 8; nb++)
            #pragma unroll
            for (int j = 0; j < 4; j++) c[mf][nb][j] = 0;

    // per stage: A 128 rows x 128B + B 128 rows x 128B = 2048 x 16B; 8 per thread
    auto load_stage = [&](int kt, int st) {
        const uint32_t sA = sbase + st * STAGEB;
        const uint32_t sB = sA + TILEB;
        #pragma unroll
        for (int i = 0; i < 4; i++) {
            int id  = tid + i * 256;
            int row = id >> 3, ch = id & 7;
            cp_async16(sA + row * ROWB + ch * 16,
                       A + (arow0 + row) * K + (size_t)kt * BK + ch * 16);
        }
        #pragma unroll
        for (int i = 0; i < 4; i++) {
            int id  = tid + i * 256;
            int row = id >> 3, ch = id & 7;
            cp_async16(sB + row * ROWB + ch * 16,
                       B + (brow0 + row) * K + (size_t)kt * BK + ch * 16);
        }
    };

    load_stage(0, 0);
    cp_commit();

    for (int kt = 0; kt < NKI; kt++) {
        cp_wait<0>();                 // stage kt resident
        __syncthreads();              // all warps finished reading stage (kt+1)&1 (iter kt-1)
        if (kt + 1 < NKI) {
            load_stage(kt + 1, (kt + 1) & 1);   // overlaps with compute below
            cp_commit();
        }

        const uint32_t sA = sbase + (kt & 1) * STAGEB;
        const uint32_t sB = sA + TILEB;
        #pragma unroll
        for (int ks = 0; ks < 4; ks++) {
            uint32_t a[2][4];
            #pragma unroll
            for (int mf = 0; mf < 2; mf++)
                ldsm_x4(a[mf], sA + (uint32_t)(wm * 32 + mf * 16) * ROWB + ks * 32 + rowsel);
            uint32_t b[4][4];
            #pragma unroll
            for (int p = 0; p < 4; p++)
                ldsm_x4(b[p], sB + (uint32_t)(wn * 64 + p * 16) * ROWB + ks * 32 + rowsel);
            #pragma unroll
            for (int mf = 0; mf < 2; mf++)
                #pragma unroll
                for (int p = 0; p < 4; p++) {
                    mma_s8(c[mf][2 * p],     a[mf], b[p][0], b[p][2]);
                    mma_s8(c[mf][2 * p + 1], a[mf], b[p][1], b[p][3]);
                }
        }
    }

    // ---------------- epilogue ----------------
    int   rows[4];
    bool  act[4];
    float sx[4];
    // erf-free amax tracking candidates (fc1 only)
    float xmx[4], xl[4], xr[4];
    #pragma unroll
    for (int mf = 0; mf < 2; mf++)
        #pragma unroll
        for (int h = 0; h < 2; h++) {
            int idx = mf * 2 + h;
            int row = mt * 128 + wm * 32 + mf * 16 + g + h * 8;
            rows[idx] = row;
            act[idx]  = (row < T_TOK);
            xmx[idx] = -1e30f; xl[idx] = -1e30f; xr[idx] = 1e30f;
            if (act[idx]) {
                if (EPI == 0) sx[idx] = ld_any(sinp, row, sindt);
                else          sx[idx] = __half2float(__float2half_rn(__fdiv_rn(g_amax[row], 127.0f)));
            } else sx[idx] = 0.0f;
        }

    #pragma unroll
    for (int nb = 0; nb < 8; nb++) {
        int col0 = nt * 128 + wn * 64 + nb * 8 + tig * 2;
        float ws0 = ld_any(wsp, col0, wsdt), ws1 = ld_any(wsp, col0 + 1, wsdt);
        float bb0 = ld_any(bp, col0, bdt),   bb1 = ld_any(bp, col0 + 1, bdt);
        #pragma unroll
        for (int mf = 0; mf < 2; mf++)
            #pragma unroll
            for (int h = 0; h < 2; h++) {
                int idx = mf * 2 + h;
                if (!act[idx]) continue;
                float v0 = (float)c[mf][nb][h * 2 + 0] * sx[idx] * ws0 + bb0;
                float v1 = (float)c[mf][nb][h * 2 + 1] * sx[idx] * ws1 + bb1;
                __half h0 = __float2half_rn(v0), h1 = __float2half_rn(v1);
                if (EPI == 0) {
                    *reinterpret_cast<__half2*>(&g_fc1[(size_t)rows[idx] * IDIM + col0]) =
                        __halves2half2(h0, h1);
                    float x0 = __half2float(h0), x1 = __half2float(h1);
                    // track candidates; gelu monotone ↓ on (-inf,x*], ↑ on [x*,inf);
                    // no fp16 grid point lies in (T1,T2) around x*
                    xmx[idx] = fmaxf(xmx[idx], fmaxf(x0, x1));
                    if (x0 <= GELU_T1) xl[idx] = fmaxf(xl[idx], x0);
                    else if (x0 < 0.0f) xr[idx] = fminf(xr[idx], x0);
                    if (x1 <= GELU_T1) xl[idx] = fmaxf(xl[idx], x1);
                    else if (x1 < 0.0f) xr[idx] = fminf(xr[idx], x1);
                } else {
                    size_t o = (size_t)rows[idx] * HDIM + col0;
                    if (outdt == 1) {
                        *reinterpret_cast<__half2*>((__half*)out_fc2 + o) = __halves2half2(h0, h1);
                    } else if (outdt == 0) {
                        ((float*)out_fc2)[o]     = __half2float(h0);
                        ((float*)out_fc2)[o + 1] = __half2float(h1);
                    } else {
                        ((__nv_bfloat16*)out_fc2)[o]     = __float2bfloat16(__half2float(h0));
                        ((__nv_bfloat16*)out_fc2)[o + 1] = __float2bfloat16(__half2float(h1));
                    }
                }
            }
    }
    if (EPI == 0) {
        #pragma unroll
        for (int idx = 0; idx < 4; idx++) {
            if (!act[idx]) continue;
            float cand = fabsf(gelu_exact(xmx[idx]));
            if (xl[idx] > -1e29f) cand = fmaxf(cand, fabsf(gelu_exact(xl[idx])));
            if (xr[idx] <  1e29f) cand = fmaxf(cand, fabsf(gelu_exact(xr[idx])));
            atomicMax(reinterpret_cast<int*>(&g_amax[rows[idx]]), __float_as_int(cand));
        }
    }
}

// ---------------- quant: fp16 fc1 -> GELU(fp32) -> int8 ----------------
__global__ void quant_kernel() {
    size_t i = (size_t)blockIdx.x * blockDim.x + threadIdx.x;   // group of 8 elems
    if (i >= (size_t)TP * IDIM / 8) return;
    size_t e = i * 8;
    int row = (int)(e / IDIM);
    uint2 outv = make_uint2(0u, 0u);
    if (row < T_TOK) {
        float am = g_amax[row];
        float s  = fmaxf(__half2float(__float2half_rn(__fdiv_rn(am, 127.0f))), 1e-8f);
        float rs = __fdiv_rn(1.0f, s);
        uint4 raw = *reinterpret_cast<const uint4*>(&g_fc1[e]);
        const __half2* hp = reinterpret_cast<const __half2*>(&raw);
        uint32_t word[2] = {0u, 0u};
        #pragma unroll
        for (int w = 0; w < 2; w++) {
            #pragma unroll
            for (int j = 0; j < 2; j++) {
                __half2 h = hp[w * 2 + j];
                float g0 = gelu_exact(__half2float(__low2half(h)));
                float g1 = gelu_exact(__half2float(__high2half(h)));
                int q0 = (int)fminf(fmaxf(rintf(g0 * rs), -128.0f), 127.0f);
                int q1 = (int)fminf(fmaxf(rintf(g1 * rs), -128.0f), 127.0f);
                word[w] |= ((uint32_t)(q0 & 255)) << (16 * j);
                word[w] |= ((uint32_t)(q1 & 255)) << (16 * j + 8);
            }
        }
        outv = make_uint2(word[0], word[1]);
    }
    *reinterpret_cast<uint2*>(g_actq + e) = outv;
}

// ---------------- host launcher ----------------
extern "C" void kernel_launch(void* const* d_in, const int* in_sizes, int n_in,
                              void* d_out, int out_size) {
    Ptrs ptrs; Szs szs;
    for (int i = 0; i < 8; i++) {
        ptrs.p[i] = (i < n_in) ? d_in[i] : nullptr;
        szs.s[i]  = (i < n_in) ? (long long)in_sizes[i] : 0;
    }

    cudaFuncSetAttribute(gemm_kernel<0>, cudaFuncAttributeMaxDynamicSharedMemorySize, SMEM_BYTES);
    cudaFuncSetAttribute(gemm_kernel<1>, cudaFuncAttributeMaxDynamicSharedMemorySize, SMEM_BYTES);

    detect_kernel<<<1, 32>>>(ptrs, szs);
    {
        size_t total = PACK_TOTAL;
        int blocks = (int)((total + 255) / 256);
        pack_kernel<<<blocks, 256>>>();
    }
    gemm_kernel<0><<<dim3(NNT_FC1, NMT), 256, SMEM_BYTES>>>(nullptr);
    {
        size_t total = (size_t)TP * IDIM / 8;
        int blocks = (int)((total + 255) / 256);
        quant_kernel<<<blocks, 256>>>();
    }
    gemm_kernel<1><<<dim3(NNT_FC2, NMT), 256, SMEM_BYTES>>>(d_out);
}

// round 14
// speedup vs baseline: 1.1334x; 1.0114x over previous
#include <cuda_runtime.h>
#include <cuda_fp16.h>
#include <cuda_bf16.h>
#include <cstdint>
#include <cstddef>

// ---------------- problem constants ----------------
#define T_TOK 2050
#define TP    2176          // 17*128 padded tokens
#define HDIM  3200          // 25*128
#define IDIM  12800         // 100*128
#define NMT   17            // TP/128
#define NNT_FC1 100         // IDIM/128
#define NNT_FC2 25          // HDIM/128

#define BK     128
#define ROWB   144          // 128 data + 16 pad -> conflict-free ldmatrix (16*i mod 128 distinct)
#define TILEB  (128 * ROWB) // 18432
#define STAGEB (2 * TILEB)  // 36864 (A tile + B tile)
#define NSTAGE 2
#define SMEM_BYTES (NSTAGE * STAGEB) // 73728 (opt-in; 2 CTAs/SM = 147KB) — proven config

// GELU stationary point x* = -0.7517916...; T1 < x* < T2, no fp16 value in (T1,T2)
#define GELU_T1 (-0.751800f)
#define GELU_T2 (-0.751785f)

// ---------------- device scratch (allocation-free) ----------------
__device__ __align__(128) int8_t g_w1q[(size_t)IDIM * HDIM];   // [I][H] int8
__device__ __align__(128) int8_t g_w2q[(size_t)HDIM * IDIM];   // [H][I]
__device__ __align__(128) int8_t g_xq [(size_t)TP * HDIM];     // [TP][H]
__device__ __align__(128) int8_t g_actq[(size_t)TP * IDIM];    // [TP][I]
__device__ __align__(128) __half g_fc1 [(size_t)TP * IDIM];    // fp16 PRE-GELU fc1 [TP][I]
__device__ float g_amax[TP];

// ---------------- runtime input binding (written by detect_kernel) ----------
// roles: 0 hs, 1 scale_in, 2 w1, 3 w1_scale, 4 b1, 5 w2, 6 w2_scale, 7 b2
__device__ const void* g_ptr[8];
__device__ int g_dt[8];       // dtype: 0=f32, 1=f16, 2=bf16 (roles 1,3,4,6,7)
__device__ int g_outdt;       // output dtype, same coding

struct Ptrs { const void* p[8]; };
struct Szs  { long long s[8]; };

__device__ __forceinline__ float ld_any(const void* p, long long i, int dt) {
    if (dt == 1) return __half2float(((const __half*)p)[i]);
    if (dt == 2) return __bfloat162float(((const __nv_bfloat16*)p)[i]);
    return ((const float*)p)[i];
}

__device__ bool probe_scale(const void* p, int dt, int n) {
    for (int i = 0; i < n; i++) {
        float v = ld_any(p, i, dt);
        if (!(v > 4e-5f && v < 0.03f)) return false;   // also rejects NaN
    }
    return true;
}
__device__ bool probe_bias(const void* p, int dt, int n) {
    int neg = 0, big = 0;
    for (int i = 0; i < n; i++) {
        float v = ld_any(p, i, dt);
        if (!(v == v) || fabsf(v) > 0.5f) return false;
        if (v < 0.0f) neg++;
        if (fabsf(v) > 1e-3f) big++;
    }
    return neg > 0 && big >= n / 4;
}

__global__ void detect_kernel(Ptrs ptrs, Szs sz) {
    if (threadIdx.x != 0 || blockIdx.x != 0) return;
    int hsI = -1, sinI = -1, w[2] = {-1, -1}, p12[2] = {-1, -1}, p3[2] = {-1, -1};
    int nw = 0, n12 = 0, n3 = 0;
    for (int i = 0; i < 8; i++) {
        long long s = sz.s[i];
        if (s == (long long)T_TOK * HDIM) hsI = i;
        else if (s == T_TOK) sinI = i;
        else if (s == (long long)IDIM * HDIM) { if (nw < 2) w[nw] = i; nw++; }
        else if (s == IDIM) { if (n12 < 2) p12[n12] = i; n12++; }
        else if (s == HDIM) { if (n3 < 2) p3[n3] = i; n3++; }
    }
    int role[8], dt[8];
    for (int i = 0; i < 8; i++) { role[i] = i; dt[i] = 0; }
    dt[1] = dt[4] = dt[7] = 1;                       // fallback: dict order, f16
    if (hsI >= 0 && sinI >= 0 && nw == 2 && n12 == 2 && n3 == 2) {
        role[0] = hsI; role[1] = sinI; role[2] = w[0]; role[5] = w[1];
        int prA[2] = { p12[0], p3[0] }, prB[2] = { p12[1], p3[1] };
        int roleS[2] = { 3, 6 }, roleB[2] = { 4, 7 };
        for (int q = 0; q < 2; q++) {
            int a = prA[q], b = prB[q];
            int si = -1, sdt = 0;
            for (int d = 0; d < 3 && si < 0; d++) {          // try f32, f16, bf16
                if      (probe_scale(ptrs.p[a], d, 256)) { si = a; sdt = d; }
                else if (probe_scale(ptrs.p[b], d, 256)) { si = b; sdt = d; }
            }
            if (si < 0) { si = a; sdt = 0; }
            int bi = (si == a) ? b : a;
            int bdt;
            if      (probe_bias(ptrs.p[bi], 1, 256)) bdt = 1;
            else if (probe_bias(ptrs.p[bi], 0, 256)) bdt = 0;
            else if (probe_bias(ptrs.p[bi], 2, 256)) bdt = 2;
            else bdt = 1;
            role[roleS[q]] = si; dt[roleS[q]] = sdt;
            role[roleB[q]] = bi; dt[roleB[q]] = bdt;
        }
        int sdt = 1;
        if      (probe_scale(ptrs.p[sinI], 1, 256)) sdt = 1;
        else if (probe_scale(ptrs.p[sinI], 0, 256)) sdt = 0;
        else if (probe_scale(ptrs.p[sinI], 2, 256)) sdt = 2;
        dt[1] = sdt;
    }
    for (int i = 0; i < 8; i++) { g_ptr[i] = ptrs.p[role[i]]; g_dt[i] = dt[i]; }
    g_outdt = dt[4];
}

// ---------------- PTX helpers ----------------
__device__ __forceinline__ void cp_async16(uint32_t dst, const void* src) {
    asm volatile("cp.async.cg.shared.global [%0], [%1], 16;" :: "r"(dst), "l"(src) : "memory");
}
__device__ __forceinline__ void cp_commit() {
    asm volatile("cp.async.commit_group;" ::: "memory");
}
template <int N>
__device__ __forceinline__ void cp_wait() {
    asm volatile("cp.async.wait_group %0;" :: "n"(N) : "memory");
}
__device__ __forceinline__ uint32_t smem_u32(const void* p) {
    uint32_t a;
    asm("{ .reg .u64 t; cvta.to.shared.u64 t, %1; cvt.u32.u64 %0, t; }" : "=r"(a) : "l"(p));
    return a;
}
__device__ __forceinline__ void ldsm_x4(uint32_t* r, uint32_t addr) {
    asm volatile("ldmatrix.sync.aligned.m8n8.x4.shared.b16 {%0,%1,%2,%3}, [%4];"
                 : "=r"(r[0]), "=r"(r[1]), "=r"(r[2]), "=r"(r[3]) : "r"(addr));
}
__device__ __forceinline__ void mma_s8(int* c, const uint32_t* a, uint32_t b0, uint32_t b1) {
    asm volatile(
        "mma.sync.aligned.m16n8k32.row.col.s32.s8.s8.s32 "
        "{%0,%1,%2,%3}, {%4,%5,%6,%7}, {%8,%9}, {%0,%1,%2,%3};"
        : "+r"(c[0]), "+r"(c[1]), "+r"(c[2]), "+r"(c[3])
        : "r"(a[0]), "r"(a[1]), "r"(a[2]), "r"(a[3]), "r"(b0), "r"(b1));
}
__device__ __forceinline__ float gelu_exact(float x) {
    return 0.5f * x * (1.0f + erff(x * 0.70710678118654752440f));
}

// ---------------- pre-pack: w1 + x int32 -> int8, amax reset (w2 deferred) ----
#define NW_GRP ((size_t)IDIM * HDIM / 4)
#define NX_GRP ((size_t)T_TOK * HDIM / 4)
#define PACK_TOTAL (NW_GRP + NX_GRP + TP)

__global__ void pack_kernel() {
    size_t i = (size_t)blockIdx.x * blockDim.x + threadIdx.x;
    if (i >= PACK_TOTAL) return;
    if (i < NW_GRP + NX_GRP) {
        const int* src;
        int8_t* dst;
        size_t g;
        if (i < NW_GRP) { src = (const int*)g_ptr[2]; dst = g_w1q; g = i; }
        else            { src = (const int*)g_ptr[0]; dst = g_xq;  g = i - NW_GRP; }
        // evict-first streaming read: keep L2 free for packed weights
        int4 v = __ldcs(reinterpret_cast<const int4*>(src + g * 4));
        uint32_t packed = (v.x & 255) | ((v.y & 255) << 8) | ((v.z & 255) << 16) | ((uint32_t)v.w << 24);
        *reinterpret_cast<uint32_t*>(dst + g * 4) = packed;
    } else {
        g_amax[i - (NW_GRP + NX_GRP)] = 0.0f;
    }
}

// ---------------- int8 tensor-core GEMM, BM=BN=128, BK=128, 256 thr, 2-stage ----
// Warps 4(m) x 2(n), warp tile 32x64 (MF=2, NB=8). 2 CTAs/SM. (proven skeleton)
// EPI==0: fc1 (A=g_xq, B=g_w1q, K=H)  -> fp16 PRE-GELU fc1 in g_fc1 + amax (erf-free tracking)
// EPI==1: fc2 (A=g_actq, B=g_w2q, K=I) -> d_out (dtype per g_outdt)
template <int EPI>
__global__ __launch_bounds__(256, 2) void gemm_kernel(void* out_fc2)
{
    constexpr int K   = (EPI == 0) ? HDIM : IDIM;
    constexpr int NKI = K / BK;                       // fc1: 25, fc2: 100
    const int8_t* __restrict__ A = (EPI == 0) ? g_xq  : g_actq;
    const int8_t* __restrict__ B = (EPI == 0) ? g_w1q : g_w2q;

    const void* wsp  = g_ptr[(EPI == 0) ? 3 : 6]; const int wsdt = g_dt[(EPI == 0) ? 3 : 6];
    const void* bp   = g_ptr[(EPI == 0) ? 4 : 7]; const int bdt  = g_dt[(EPI == 0) ? 4 : 7];
    const void* sinp = g_ptr[1];                  const int sindt = g_dt[1];
    const int outdt = g_outdt;

    extern __shared__ uint8_t smem8[];
    const uint32_t sbase = smem_u32(smem8);

    const int tid  = threadIdx.x;
    const int wid  = tid >> 5, lane = tid & 31;
    const int wm   = wid >> 1, wn = wid & 1;          // 4(m) x 2(n) warps; warp tile 32x64
    const int g    = lane >> 2, tig = lane & 3;
    const int nt   = blockIdx.x, mt = blockIdx.y;

    const size_t arow0 = (size_t)mt * 128;
    const size_t brow0 = (size_t)nt * 128;

    // ldmatrix lane -> (row, 16B column) selector
    const uint32_t rowsel = (uint32_t)(lane & 15) * ROWB + (uint32_t)(lane >> 4) * 16;

    int c[2][8][4];
    #pragma unroll
    for (int mf = 0; mf < 2; mf++)
        #pragma unroll
        for (int nb = 0; nb < 8; nb++)
            #pragma unroll
            for (int j = 0; j < 4; j++) c[mf][nb][j] = 0;

    // per stage: A 128 rows x 128B + B 128 rows x 128B = 2048 x 16B; 8 per thread
    auto load_stage = [&](int kt, int st) {
        const uint32_t sA = sbase + st * STAGEB;
        const uint32_t sB = sA + TILEB;
        #pragma unroll
        for (int i = 0; i < 4; i++) {
            int id  = tid + i * 256;
            int row = id >> 3, ch = id & 7;
            cp_async16(sA + row * ROWB + ch * 16,
                       A + (arow0 + row) * K + (size_t)kt * BK + ch * 16);
        }
        #pragma unroll
        for (int i = 0; i < 4; i++) {
            int id  = tid + i * 256;
            int row = id >> 3, ch = id & 7;
            cp_async16(sB + row * ROWB + ch * 16,
                       B + (brow0 + row) * K + (size_t)kt * BK + ch * 16);
        }
    };

    load_stage(0, 0);
    cp_commit();

    for (int kt = 0; kt < NKI; kt++) {
        cp_wait<0>();                 // stage kt resident
        __syncthreads();              // all warps finished reading stage (kt+1)&1 (iter kt-1)
        if (kt + 1 < NKI) {
            load_stage(kt + 1, (kt + 1) & 1);   // overlaps with compute below
            cp_commit();
        }

        const uint32_t sA = sbase + (kt & 1) * STAGEB;
        const uint32_t sB = sA + TILEB;
        #pragma unroll
        for (int ks = 0; ks < 4; ks++) {
            uint32_t a[2][4];
            #pragma unroll
            for (int mf = 0; mf < 2; mf++)
                ldsm_x4(a[mf], sA + (uint32_t)(wm * 32 + mf * 16) * ROWB + ks * 32 + rowsel);
            uint32_t b[4][4];
            #pragma unroll
            for (int p = 0; p < 4; p++)
                ldsm_x4(b[p], sB + (uint32_t)(wn * 64 + p * 16) * ROWB + ks * 32 + rowsel);
            #pragma unroll
            for (int mf = 0; mf < 2; mf++)
                #pragma unroll
                for (int p = 0; p < 4; p++) {
                    mma_s8(c[mf][2 * p],     a[mf], b[p][0], b[p][2]);
                    mma_s8(c[mf][2 * p + 1], a[mf], b[p][1], b[p][3]);
                }
        }
    }

    // ---------------- epilogue ----------------
    int   rows[4];
    bool  act[4];
    float sx[4];
    // erf-free amax tracking candidates (fc1 only)
    float xmx[4], xl[4], xr[4];
    #pragma unroll
    for (int mf = 0; mf < 2; mf++)
        #pragma unroll
        for (int h = 0; h < 2; h++) {
            int idx = mf * 2 + h;
            int row = mt * 128 + wm * 32 + mf * 16 + g + h * 8;
            rows[idx] = row;
            act[idx]  = (row < T_TOK);
            xmx[idx] = -1e30f; xl[idx] = -1e30f; xr[idx] = 1e30f;
            if (act[idx]) {
                if (EPI == 0) sx[idx] = ld_any(sinp, row, sindt);
                else          sx[idx] = __half2float(__float2half_rn(__fdiv_rn(g_amax[row], 127.0f)));
            } else sx[idx] = 0.0f;
        }

    #pragma unroll
    for (int nb = 0; nb < 8; nb++) {
        int col0 = nt * 128 + wn * 64 + nb * 8 + tig * 2;
        float ws0 = ld_any(wsp, col0, wsdt), ws1 = ld_any(wsp, col0 + 1, wsdt);
        float bb0 = ld_any(bp, col0, bdt),   bb1 = ld_any(bp, col0 + 1, bdt);
        #pragma unroll
        for (int mf = 0; mf < 2; mf++)
            #pragma unroll
            for (int h = 0; h < 2; h++) {
                int idx = mf * 2 + h;
                if (!act[idx]) continue;
                float v0 = (float)c[mf][nb][h * 2 + 0] * sx[idx] * ws0 + bb0;
                float v1 = (float)c[mf][nb][h * 2 + 1] * sx[idx] * ws1 + bb1;
                __half h0 = __float2half_rn(v0), h1 = __float2half_rn(v1);
                if (EPI == 0) {
                    *reinterpret_cast<__half2*>(&g_fc1[(size_t)rows[idx] * IDIM + col0]) =
                        __halves2half2(h0, h1);
                    float x0 = __half2float(h0), x1 = __half2float(h1);
                    // track candidates; gelu monotone ↓ on (-inf,x*], ↑ on [x*,inf);
                    // no fp16 grid point lies in (T1,T2) around x*
                    xmx[idx] = fmaxf(xmx[idx], fmaxf(x0, x1));
                    if (x0 <= GELU_T1) xl[idx] = fmaxf(xl[idx], x0);
                    else if (x0 < 0.0f) xr[idx] = fminf(xr[idx], x0);
                    if (x1 <= GELU_T1) xl[idx] = fmaxf(xl[idx], x1);
                    else if (x1 < 0.0f) xr[idx] = fminf(xr[idx], x1);
                } else {
                    size_t o = (size_t)rows[idx] * HDIM + col0;
                    if (outdt == 1) {
                        *reinterpret_cast<__half2*>((__half*)out_fc2 + o) = __halves2half2(h0, h1);
                    } else if (outdt == 0) {
                        ((float*)out_fc2)[o]     = __half2float(h0);
                        ((float*)out_fc2)[o + 1] = __half2float(h1);
                    } else {
                        ((__nv_bfloat16*)out_fc2)[o]     = __float2bfloat16(__half2float(h0));
                        ((__nv_bfloat16*)out_fc2)[o + 1] = __float2bfloat16(__half2float(h1));
                    }
                }
            }
    }
    if (EPI == 0) {
        #pragma unroll
        for (int idx = 0; idx < 4; idx++) {
            if (!act[idx]) continue;
            float cand = fabsf(gelu_exact(xmx[idx]));
            if (xl[idx] > -1e29f) cand = fmaxf(cand, fabsf(gelu_exact(xl[idx])));
            if (xr[idx] <  1e29f) cand = fmaxf(cand, fabsf(gelu_exact(xr[idx])));
            atomicMax(reinterpret_cast<int*>(&g_amax[rows[idx]]), __float_as_int(cand));
        }
    }
}

// ---------------- quant + w2 pack (fused; orthogonal pipes) ----------------
// Blocks [0, W2PACK_BLOCKS): grid-stride w2 int32->int8 (DRAM-bound; hides under
// the ALU-bound quant work — quant measured at only 16.9% DRAM).
// Blocks [W2PACK_BLOCKS, ...): fp16 fc1 -> GELU(fp32) -> int8.
// w2 is consumed by gemm<1>, which launches after this kernel -> ordering free.
#define W2PACK_BLOCKS 2048
#define QUANT_GROUPS ((size_t)TP * IDIM / 8)
#define QUANT_BLOCKS ((int)((QUANT_GROUPS + 255) / 256))

__global__ void quant_kernel() {
    if (blockIdx.x < W2PACK_BLOCKS) {
        const int* __restrict__ src = (const int*)g_ptr[5];
        size_t i0 = (size_t)blockIdx.x * blockDim.x + threadIdx.x;
        size_t stride = (size_t)W2PACK_BLOCKS * blockDim.x;
        for (size_t g = i0; g < NW_GRP; g += stride) {
            int4 v = __ldcs(reinterpret_cast<const int4*>(src + g * 4));
            uint32_t packed = (v.x & 255) | ((v.y & 255) << 8) |
                              ((v.z & 255) << 16) | ((uint32_t)v.w << 24);
            *reinterpret_cast<uint32_t*>(g_w2q + g * 4) = packed;
        }
        return;
    }
    size_t i = (size_t)(blockIdx.x - W2PACK_BLOCKS) * blockDim.x + threadIdx.x;  // group of 8 elems
    if (i >= QUANT_GROUPS) return;
    size_t e = i * 8;
    int row = (int)(e / IDIM);
    uint2 outv = make_uint2(0u, 0u);
    if (row < T_TOK) {
        float am = g_amax[row];
        float s  = fmaxf(__half2float(__float2half_rn(__fdiv_rn(am, 127.0f))), 1e-8f);
        float rs = __fdiv_rn(1.0f, s);
        uint4 raw = *reinterpret_cast<const uint4*>(&g_fc1[e]);
        const __half2* hp = reinterpret_cast<const __half2*>(&raw);
        uint32_t word[2] = {0u, 0u};
        #pragma unroll
        for (int w = 0; w < 2; w++) {
            #pragma unroll
            for (int j = 0; j < 2; j++) {
                __half2 h = hp[w * 2 + j];
                float g0 = gelu_exact(__half2float(__low2half(h)));
                float g1 = gelu_exact(__half2float(__high2half(h)));
                int q0 = (int)fminf(fmaxf(rintf(g0 * rs), -128.0f), 127.0f);
                int q1 = (int)fminf(fmaxf(rintf(g1 * rs), -128.0f), 127.0f);
                word[w] |= ((uint32_t)(q0 & 255)) << (16 * j);
                word[w] |= ((uint32_t)(q1 & 255)) << (16 * j + 8);
            }
        }
        outv = make_uint2(word[0], word[1]);
    }
    *reinterpret_cast<uint2*>(g_actq + e) = outv;
}

// ---------------- host launcher ----------------
extern "C" void kernel_launch(void* const* d_in, const int* in_sizes, int n_in,
                              void* d_out, int out_size) {
    Ptrs ptrs; Szs szs;
    for (int i = 0; i < 8; i++) {
        ptrs.p[i] = (i < n_in) ? d_in[i] : nullptr;
        szs.s[i]  = (i < n_in) ? (long long)in_sizes[i] : 0;
    }

    cudaFuncSetAttribute(gemm_kernel<0>, cudaFuncAttributeMaxDynamicSharedMemorySize, SMEM_BYTES);
    cudaFuncSetAttribute(gemm_kernel<1>, cudaFuncAttributeMaxDynamicSharedMemorySize, SMEM_BYTES);

    detect_kernel<<<1, 32>>>(ptrs, szs);
    {
        size_t total = PACK_TOTAL;
        int blocks = (int)((total + 255) / 256);
        pack_kernel<<<blocks, 256>>>();
    }
    gemm_kernel<0><<<dim3(NNT_FC1, NMT), 256, SMEM_BYTES>>>(nullptr);
    quant_kernel<<<W2PACK_BLOCKS + QUANT_BLOCKS, 256>>>();
    gemm_kernel<1><<<dim3(NNT_FC2, NMT), 256, SMEM_BYTES>>>(d_out);
}